// round 15
// baseline (speedup 1.0000x reference)
#include <cuda_runtime.h>
#include <cuda_fp16.h>
#include <cstdint>

#define HH 4
#define BB 4
#define NN 2048
#define FF 128
#define UU 64
#define LOG2E 1.4426950408889634f

#define JC 4
#define JCHUNK 512
#define NTILE (BB*16*JC)   // 256 (b,it,jc) tiles
#define BLD 72             // proj B tile row stride in halves (144 B): conflict-free
#define BUFB (128*BLD*2)   // one B buffer: 18432 bytes

// ---------------- scratch ----------------------------------------------------
__device__ __half    g_proj[HH*BB*NN*UU];     // 4 MB  fp16 projections
__device__ float     g_s[HH*BB*NN];
__device__ float     g_spos[HH*BB];
__device__ float     g_sneg[HH*BB];
__device__ unsigned  g_mask[BB*NN*64];        // 2 MB packed adjacency bitmask
__device__ __half    g_Opart[8388608];        // [NTILE][H][128][64] fp16 partials
__device__ float     g_Zpart[NTILE*HH*128];

__device__ __forceinline__ uint32_t smem_u32(const void* p) {
    uint32_t a;
    asm("{ .reg .u64 t; cvta.to.shared.u64 t, %1; cvt.u32.u64 %0, t; }" : "=r"(a) : "l"(p));
    return a;
}

__device__ __forceinline__ uint32_t ex2pack(float x, float y) {
    __half2 hh = __floats2half2_rn(x, y);
    uint32_t u = *reinterpret_cast<uint32_t*>(&hh);
    asm("ex2.approx.f16x2 %0, %0;" : "+r"(u));
    return u;
}
__device__ __forceinline__ uint32_t hmul2u(uint32_t e, uint32_t m) {
    __half2 a = *reinterpret_cast<__half2*>(&e);
    __half2 b = *reinterpret_cast<__half2*>(&m);
    __half2 c = __hmul2(a, b);
    return *reinterpret_cast<uint32_t*>(&c);
}

#define MMA_F16(d, a0,a1,a2,a3, b0,b1) \
    asm volatile("mma.sync.aligned.m16n8k16.row.col.f32.f16.f16.f32 " \
        "{%0,%1,%2,%3}, {%4,%5,%6,%7}, {%8,%9}, {%0,%1,%2,%3};" \
        : "+f"((d)[0]), "+f"((d)[1]), "+f"((d)[2]), "+f"((d)[3]) \
        : "r"(a0), "r"(a1), "r"(a2), "r"(a3), "r"(b0), "r"(b1))

#define LDSM_X4_TRANS(r0,r1,r2,r3, addr) \
    asm volatile("ldmatrix.sync.aligned.m8n8.x4.trans.shared.b16 {%0,%1,%2,%3}, [%4];" \
        : "=r"(r0), "=r"(r1), "=r"(r2), "=r"(r3) : "r"(addr))

#define CP_ASYNC_16(dst_u32, src) \
    asm volatile("cp.async.cg.shared.global [%0], [%1], 16;" \
        :: "r"(dst_u32), "l"(src) : "memory")
#define CP_ASYNC_COMMIT() asm volatile("cp.async.commit_group;" ::: "memory")
#define CP_ASYNC_WAIT0()  asm volatile("cp.async.wait_group 0;" ::: "memory")

// ---------------- Kernel 1: proj = relu(x@W + b), s = proj.a_w + a_b --------
__global__ __launch_bounds__(128) void k_proj(const float* __restrict__ x,
                                              const float* __restrict__ W,
                                              const float* __restrict__ bias,
                                              const float* __restrict__ a_w,
                                              const float* __restrict__ a_b)
{
    __shared__ __align__(16) float Wsm[16][UU];
    __shared__ float xsm[128][17];
    __shared__ float bsm[UU], awsm[UU];

    int h = blockIdx.z, b = blockIdx.y;
    int n0 = blockIdx.x * 128;
    int tid = threadIdx.x;

    if (tid < UU) { bsm[tid] = bias[h*UU + tid]; awsm[tid] = a_w[h*UU + tid]; }

    unsigned long long acc2[32];
    #pragma unroll
    for (int p = 0; p < 32; p++) acc2[p] = 0ULL;

    const float* xb = x + ((size_t)b*NN + n0)*FF;
    const float* Wb = W + (size_t)h*FF*UU;

    for (int fc = 0; fc < FF; fc += 16) {
        __syncthreads();
        for (int k = tid; k < 16*UU; k += 128)
            Wsm[k>>6][k&63] = Wb[(size_t)(fc + (k>>6))*UU + (k&63)];
        for (int k = tid; k < 128*16; k += 128) {
            int r = k >> 4, f = k & 15;
            xsm[r][f] = xb[(size_t)r*FF + fc + f];
        }
        __syncthreads();
        #pragma unroll
        for (int f = 0; f < 16; f++) {
            float xv = xsm[tid][f];
            unsigned long long xv2;
            asm("mov.b64 %0, {%1, %1};" : "=l"(xv2) : "f"(xv));
            #pragma unroll
            for (int p = 0; p < 32; p += 2) {
                ulonglong2 w2 = *(const ulonglong2*)&Wsm[f][p*2];
                asm("fma.rn.f32x2 %0, %1, %2, %0;" : "+l"(acc2[p])   : "l"(xv2), "l"(w2.x));
                asm("fma.rn.f32x2 %0, %1, %2, %0;" : "+l"(acc2[p+1]) : "l"(xv2), "l"(w2.y));
            }
        }
    }

    float s = 0.f;
    __half2* pout = (__half2*)(g_proj + ((size_t)(h*BB+b)*NN + n0 + tid)*UU);
    #pragma unroll
    for (int p = 0; p < 32; p++) {
        float a0, a1;
        asm("mov.b64 {%0,%1}, %2;" : "=f"(a0), "=f"(a1) : "l"(acc2[p]));
        float p0 = fmaxf(a0 + bsm[2*p],   0.f);
        float p1 = fmaxf(a1 + bsm[2*p+1], 0.f);
        s = fmaf(p0, awsm[2*p],   s);
        s = fmaf(p1, awsm[2*p+1], s);
        pout[p] = __floats2half2_rn(p0, p1);
    }
    s += a_b[h];
    g_s[(size_t)(h*BB+b)*NN + n0 + tid] = s;
}

// ---------------- Kernel 1b: per-(h,b) max/min of s --------------------------
__global__ __launch_bounds__(256) void k_minmax()
{
    __shared__ float smx[256], smn[256];
    int hb = blockIdx.x, tid = threadIdx.x;
    float mx = -1e30f, mn = 1e30f;
    for (int k = tid; k < NN; k += 256) {
        float v = g_s[(size_t)hb*NN + k];
        mx = fmaxf(mx, v); mn = fminf(mn, v);
    }
    smx[tid] = mx; smn[tid] = mn;
    __syncthreads();
    for (int off = 128; off > 0; off >>= 1) {
        if (tid < off) {
            smx[tid] = fmaxf(smx[tid], smx[tid+off]);
            smn[tid] = fminf(smn[tid], smn[tid+off]);
        }
        __syncthreads();
    }
    if (tid == 0) { g_spos[hb] = smx[0]; g_sneg[hb] = smn[0]; }
}

// ---------------- Kernel 1c: adj -> bitmask via ballot (1 warp / row) -------
__global__ __launch_bounds__(256) void k_mask(const int* __restrict__ adj)
{
    int wid = threadIdx.x >> 5, lane = threadIdx.x & 31;
    int row = blockIdx.x*8 + wid;          // 0..8191 = b*NN + i
    const int* ap = adj + (size_t)row*NN + lane;
    unsigned* mp = g_mask + (size_t)row*64;

    #pragma unroll
    for (int t8 = 0; t8 < 8; t8++) {
        unsigned w[8];
        #pragma unroll
        for (int k = 0; k < 8; k++) {
            int v = __ldcs(ap + (t8*8 + k)*32);
            w[k] = __ballot_sync(0xffffffffu, v > 0);
        }
        if (lane == 0) {
            *(uint4*)(mp + t8*8)     = make_uint4(w[0], w[1], w[2], w[3]);
            *(uint4*)(mp + t8*8 + 4) = make_uint4(w[4], w[5], w[6], w[7]);
        }
    }
}

// ---------------- Kernel 2: per-(b,it,jc,h) unit, 1024 CTAs -----------------
#define SMEM_ATTN 39968
#define ONEH2 0x3C003C00u

__global__ __launch_bounds__(256,3) void k_attn()
{
    extern __shared__ char smem[];
    float*    s_il2e = (float*)(smem);
    float*    s_mhat = (float*)(smem + 512);
    float*    sjs    = (float*)(smem + 1024);
    unsigned* lutm   = (unsigned*)(smem + 3072);
    __half*   projB  = (__half*)(smem + 3104);
    uint32_t  projB_u32 = smem_u32(projB);

    int cidx = blockIdx.x;                 // 1024 units
    int it = cidx & 15;
    int jc = (cidx >> 4) & 3;
    int b  = (cidx >> 6) & 3;
    int h  = cidx >> 8;
    int tile = (b*16 + it)*4 + jc;

    int tid = threadIdx.x, lane = tid & 31, wid = tid >> 5;
    int g = lane >> 2, tg2 = (lane & 3)*2;

    if (tid < 4)
        lutm[tid] = ((tid & 1) ? 0x00003C00u : 0u) | ((tid & 2) ? 0x3C000000u : 0u);

    if (tid < 128) {
        float sv = g_s[(size_t)(h*BB+b)*NN + it*128 + tid];
        float sp = g_spos[h*BB+b], sn = g_sneg[h*BB+b];
        float mh = (sv >= 0.f) ? sv*sp : sv*sn;
        s_il2e[tid] = sv * LOG2E;
        s_mhat[tid] = mh * LOG2E;
    }
    for (int idx = tid; idx < 512; idx += 256)
        sjs[idx] = g_s[(size_t)(h*BB+b)*NN + jc*JCHUNK + idx];

    auto loadB = [&](int jtn, int bufn) {
        const char* psrc = (const char*)(g_proj +
            ((size_t)(h*BB+b)*NN + jc*JCHUNK + jtn*128)*UU);
        uint32_t pdst = projB_u32 + (uint32_t)bufn*BUFB;
        #pragma unroll
        for (int c = 0; c < 4; c++) {
            int k = tid + c*256;
            int ro = k >> 3, cg = k & 7;
            CP_ASYNC_16(pdst + (uint32_t)(ro*BLD + cg*8)*2, psrc + (size_t)k*16);
        }
        CP_ASYNC_COMMIT();
    };

    loadB(0, 0);
    CP_ASYNC_WAIT0();
    __syncthreads();

    int r_lo = wid*16 + g;
    int r_hi = r_lo + 8;

    int ldm_row = (lane & 7) + ((lane >> 3) & 1)*8;
    uint32_t ldm_off = (uint32_t)(ldm_row*BLD + (lane >> 4)*8) * 2;

    const uint4* mrow_lo = (const uint4*)(g_mask + ((size_t)(b*NN + it*128 + r_lo))*64 + jc*16);
    const uint4* mrow_hi = (const uint4*)(g_mask + ((size_t)(b*NN + it*128 + r_hi))*64 + jc*16);

    float srl_lo = s_il2e[r_lo], nmh_lo = -s_mhat[r_lo];
    float srl_hi = s_il2e[r_hi], nmh_hi = -s_mhat[r_hi];

    float acc[8][4];
    float zac[4];
    #pragma unroll
    for (int q = 0; q < 8; q++)
        #pragma unroll
        for (int i = 0; i < 4; i++) acc[q][i] = 0.f;
    #pragma unroll
    for (int i = 0; i < 4; i++) zac[i] = 0.f;

    #pragma unroll
    for (int jt = 0; jt < 4; jt++) {
        uint32_t bbase = projB_u32 + (uint32_t)(jt & 1)*BUFB + ldm_off;

        if (jt) { CP_ASYNC_WAIT0(); __syncthreads(); }
        if (jt + 1 < 4) loadB(jt + 1, (jt + 1) & 1);

        uint4 mw_lo = mrow_lo[jt];
        uint4 mw_hi = mrow_hi[jt];
        const float* sjp = sjs + jt*128;

        #pragma unroll
        for (int w = 0; w < 4; w++) {
            unsigned wl = (w==0)?mw_lo.x:(w==1)?mw_lo.y:(w==2)?mw_lo.z:mw_lo.w;
            unsigned wh = (w==0)?mw_hi.x:(w==1)?mw_hi.y:(w==2)?mw_hi.z:mw_hi.w;
            #pragma unroll
            for (int k2 = 0; k2 < 2; k2++) {
                int ks = w*2 + k2;
                int c0 = ks*16 + tg2;
                float2 sj0 = *(const float2*)(sjp + c0);
                float2 sj1 = *(const float2*)(sjp + c0 + 8);
                int sh = k2*16 + tg2;

                uint32_t a0 = hmul2u(
                    ex2pack(fmaf(srl_lo, sj0.x, nmh_lo), fmaf(srl_lo, sj0.y, nmh_lo)),
                    lutm[(wl >> sh) & 3]);
                uint32_t a1 = hmul2u(
                    ex2pack(fmaf(srl_hi, sj0.x, nmh_hi), fmaf(srl_hi, sj0.y, nmh_hi)),
                    lutm[(wh >> sh) & 3]);
                uint32_t a2 = hmul2u(
                    ex2pack(fmaf(srl_lo, sj1.x, nmh_lo), fmaf(srl_lo, sj1.y, nmh_lo)),
                    lutm[(wl >> (sh+8)) & 3]);
                uint32_t a3 = hmul2u(
                    ex2pack(fmaf(srl_hi, sj1.x, nmh_hi), fmaf(srl_hi, sj1.y, nmh_hi)),
                    lutm[(wh >> (sh+8)) & 3]);

                uint32_t kroff = (uint32_t)(ks*16*BLD*2);
                #pragma unroll
                for (int nt = 0; nt < 4; nt++) {
                    uint32_t r0, r1, r2, r3;
                    LDSM_X4_TRANS(r0, r1, r2, r3, bbase + kroff + (uint32_t)(nt*16*2));
                    MMA_F16(acc[2*nt],   a0, a1, a2, a3, r0, r1);
                    MMA_F16(acc[2*nt+1], a0, a1, a2, a3, r2, r3);
                }
                MMA_F16(zac, a0, a1, a2, a3, ONEH2, ONEH2);
            }
        }
    }

    __half* ob = g_Opart + (((size_t)tile*HH + h)*128 + wid*16)*64;
    #pragma unroll
    for (int q = 0; q < 8; q++) {
        *(__half2*)(ob + (size_t)g*64     + q*8 + tg2) = __floats2half2_rn(acc[q][0], acc[q][1]);
        *(__half2*)(ob + (size_t)(g+8)*64 + q*8 + tg2) = __floats2half2_rn(acc[q][2], acc[q][3]);
    }
    if ((lane & 3) == 0) {
        float* zb = g_Zpart + ((size_t)tile*HH + h)*128;
        zb[r_lo] = zac[0];
        zb[r_hi] = zac[2];
    }
}

// ---------------- Kernel 3: combine, divide, head-mean (1 thread / u-pair) --
__global__ __launch_bounds__(256) void k_final(float* __restrict__ out)
{
    int idx = blockIdx.x*256 + threadIdx.x;      // 0 .. 262143
    int u2 = idx & 31;
    int n  = (idx >> 5) & 2047;
    int b  = idx >> 16;
    int it = n >> 7, r = n & 127;

    float ax = 0.f, ay = 0.f;
    #pragma unroll
    for (int h = 0; h < HH; h++) {
        float z = 0.f, nx = 0.f, ny = 0.f;
        #pragma unroll
        for (int jcc = 0; jcc < JC; jcc++) {
            int c = (b*16 + it)*4 + jcc;
            size_t base = ((size_t)c*HH + h)*128 + r;
            z += g_Zpart[base];
            __half2 v = *(const __half2*)(g_Opart + base*64 + u2*2);
            float2 f = __half22float2(v);
            nx += f.x; ny += f.y;
        }
        float rz = __frcp_rn(z);
        ax = fmaf(nx, rz, ax);
        ay = fmaf(ny, rz, ay);
    }
    *(float2*)(out + ((size_t)b*NN + n)*64 + u2*2) = make_float2(0.25f*ax, 0.25f*ay);
}

// ---------------- launch: fork k_mask parallel to k_proj+k_minmax -----------
extern "C" void kernel_launch(void* const* d_in, const int* in_sizes, int n_in,
                              void* d_out, int out_size)
{
    const float* x   = (const float*)d_in[0];
    const int*   adj = (const int*)d_in[1];
    const float* W   = (const float*)d_in[2];
    const float* bia = (const float*)d_in[3];
    const float* aw  = (const float*)d_in[4];
    const float* ab  = (const float*)d_in[5];
    float* out = (float*)d_out;
    (void)in_sizes; (void)n_in; (void)out_size;

    cudaFuncSetAttribute(k_attn, cudaFuncAttributeMaxDynamicSharedMemorySize, SMEM_ATTN);

    // fork a side stream (capture-safe fork/join pattern); created fresh per
    // call (kernel_launch runs only for correctness + capture), not destroyed
    // mid-capture.
    cudaStream_t s2;
    cudaStreamCreateWithFlags(&s2, cudaStreamNonBlocking);
    cudaEvent_t eFork, eJoin;
    cudaEventCreateWithFlags(&eFork, cudaEventDisableTiming);
    cudaEventCreateWithFlags(&eJoin, cudaEventDisableTiming);

    cudaEventRecord(eFork, 0);
    cudaStreamWaitEvent(s2, eFork, 0);

    k_mask<<<1024, 256, 0, s2>>>(adj);          // DRAM-bound branch

    dim3 g1(NN/128, BB, HH);
    k_proj<<<g1, 128>>>(x, W, bia, aw, ab);     // FFMA-bound branch
    k_minmax<<<HH*BB, 256>>>();

    cudaEventRecord(eJoin, s2);
    cudaStreamWaitEvent(0, eJoin, 0);           // join before k_attn

    k_attn<<<1024, 256, SMEM_ATTN>>>();
    k_final<<<(BB*NN*UU/2)/256, 256>>>(out);
}

// round 16
// speedup vs baseline: 1.2357x; 1.2357x over previous
#include <cuda_runtime.h>
#include <cuda_fp16.h>
#include <cstdint>

#define HH 4
#define BB 4
#define NN 2048
#define FF 128
#define UU 64
#define LOG2E 1.4426950408889634f

#define JC 4
#define JCHUNK 512
#define NTILE (BB*16*JC)   // 256 (b,it,jc) tiles
#define BLD 72             // proj B tile row stride in halves (144 B): conflict-free
#define BUFB (128*BLD*2)   // one B buffer: 18432 bytes

// ---------------- scratch ----------------------------------------------------
__device__ __half    g_proj[HH*BB*NN*UU];     // 4 MB  fp16 projections
__device__ float     g_s[HH*BB*NN];
__device__ float     g_spos[HH*BB];
__device__ float     g_sneg[HH*BB];
__device__ unsigned  g_mask[BB*NN*64];        // 2 MB packed adjacency bitmask
__device__ __half    g_Opart[8388608];        // [NTILE][H][128][64] fp16 partials
__device__ float     g_Zpart[NTILE*HH*128];

__device__ __forceinline__ uint32_t smem_u32(const void* p) {
    uint32_t a;
    asm("{ .reg .u64 t; cvta.to.shared.u64 t, %1; cvt.u32.u64 %0, t; }" : "=r"(a) : "l"(p));
    return a;
}

__device__ __forceinline__ uint32_t ex2pack(float x, float y) {
    __half2 hh = __floats2half2_rn(x, y);
    uint32_t u = *reinterpret_cast<uint32_t*>(&hh);
    asm("ex2.approx.f16x2 %0, %0;" : "+r"(u));
    return u;
}
__device__ __forceinline__ uint32_t hmul2u(uint32_t e, uint32_t m) {
    __half2 a = *reinterpret_cast<__half2*>(&e);
    __half2 b = *reinterpret_cast<__half2*>(&m);
    __half2 c = __hmul2(a, b);
    return *reinterpret_cast<uint32_t*>(&c);
}

#define MMA_F16(d, a0,a1,a2,a3, b0,b1) \
    asm volatile("mma.sync.aligned.m16n8k16.row.col.f32.f16.f16.f32 " \
        "{%0,%1,%2,%3}, {%4,%5,%6,%7}, {%8,%9}, {%0,%1,%2,%3};" \
        : "+f"((d)[0]), "+f"((d)[1]), "+f"((d)[2]), "+f"((d)[3]) \
        : "r"(a0), "r"(a1), "r"(a2), "r"(a3), "r"(b0), "r"(b1))

#define LDSM_X4_TRANS(r0,r1,r2,r3, addr) \
    asm volatile("ldmatrix.sync.aligned.m8n8.x4.trans.shared.b16 {%0,%1,%2,%3}, [%4];" \
        : "=r"(r0), "=r"(r1), "=r"(r2), "=r"(r3) : "r"(addr))

#define CP_ASYNC_16(dst_u32, src) \
    asm volatile("cp.async.cg.shared.global [%0], [%1], 16;" \
        :: "r"(dst_u32), "l"(src) : "memory")
#define CP_ASYNC_COMMIT() asm volatile("cp.async.commit_group;" ::: "memory")
#define CP_ASYNC_WAIT0()  asm volatile("cp.async.wait_group 0;" ::: "memory")

// ---------------- Kernel 1: proj = relu(x@W + b), s = proj.a_w + a_b --------
__global__ __launch_bounds__(128) void k_proj(const float* __restrict__ x,
                                              const float* __restrict__ W,
                                              const float* __restrict__ bias,
                                              const float* __restrict__ a_w,
                                              const float* __restrict__ a_b)
{
    __shared__ __align__(16) float Wsm[16][UU];
    __shared__ float xsm[128][17];
    __shared__ float bsm[UU], awsm[UU];

    int h = blockIdx.z, b = blockIdx.y;
    int n0 = blockIdx.x * 128;
    int tid = threadIdx.x;

    if (tid < UU) { bsm[tid] = bias[h*UU + tid]; awsm[tid] = a_w[h*UU + tid]; }

    unsigned long long acc2[32];
    #pragma unroll
    for (int p = 0; p < 32; p++) acc2[p] = 0ULL;

    const float* xb = x + ((size_t)b*NN + n0)*FF;
    const float* Wb = W + (size_t)h*FF*UU;

    for (int fc = 0; fc < FF; fc += 16) {
        __syncthreads();
        for (int k = tid; k < 16*UU; k += 128)
            Wsm[k>>6][k&63] = Wb[(size_t)(fc + (k>>6))*UU + (k&63)];
        for (int k = tid; k < 128*16; k += 128) {
            int r = k >> 4, f = k & 15;
            xsm[r][f] = xb[(size_t)r*FF + fc + f];
        }
        __syncthreads();
        #pragma unroll
        for (int f = 0; f < 16; f++) {
            float xv = xsm[tid][f];
            unsigned long long xv2;
            asm("mov.b64 %0, {%1, %1};" : "=l"(xv2) : "f"(xv));
            #pragma unroll
            for (int p = 0; p < 32; p += 2) {
                ulonglong2 w2 = *(const ulonglong2*)&Wsm[f][p*2];
                asm("fma.rn.f32x2 %0, %1, %2, %0;" : "+l"(acc2[p])   : "l"(xv2), "l"(w2.x));
                asm("fma.rn.f32x2 %0, %1, %2, %0;" : "+l"(acc2[p+1]) : "l"(xv2), "l"(w2.y));
            }
        }
    }

    float s = 0.f;
    __half2* pout = (__half2*)(g_proj + ((size_t)(h*BB+b)*NN + n0 + tid)*UU);
    #pragma unroll
    for (int p = 0; p < 32; p++) {
        float a0, a1;
        asm("mov.b64 {%0,%1}, %2;" : "=f"(a0), "=f"(a1) : "l"(acc2[p]));
        float p0 = fmaxf(a0 + bsm[2*p],   0.f);
        float p1 = fmaxf(a1 + bsm[2*p+1], 0.f);
        s = fmaf(p0, awsm[2*p],   s);
        s = fmaf(p1, awsm[2*p+1], s);
        pout[p] = __floats2half2_rn(p0, p1);
    }
    s += a_b[h];
    g_s[(size_t)(h*BB+b)*NN + n0 + tid] = s;
}

// ---------------- Kernel 1b: per-(h,b) max/min of s --------------------------
__global__ __launch_bounds__(256) void k_minmax()
{
    __shared__ float smx[256], smn[256];
    int hb = blockIdx.x, tid = threadIdx.x;
    float mx = -1e30f, mn = 1e30f;
    for (int k = tid; k < NN; k += 256) {
        float v = g_s[(size_t)hb*NN + k];
        mx = fmaxf(mx, v); mn = fminf(mn, v);
    }
    smx[tid] = mx; smn[tid] = mn;
    __syncthreads();
    for (int off = 128; off > 0; off >>= 1) {
        if (tid < off) {
            smx[tid] = fmaxf(smx[tid], smx[tid+off]);
            smn[tid] = fminf(smn[tid], smn[tid+off]);
        }
        __syncthreads();
    }
    if (tid == 0) { g_spos[hb] = smx[0]; g_sneg[hb] = smn[0]; }
}

// ---------------- Kernel 1c: adj -> bitmask via ballot (1 warp / row) -------
__global__ __launch_bounds__(256) void k_mask(const int* __restrict__ adj)
{
    int wid = threadIdx.x >> 5, lane = threadIdx.x & 31;
    int row = blockIdx.x*8 + wid;          // 0..8191 = b*NN + i
    const int* ap = adj + (size_t)row*NN + lane;
    unsigned* mp = g_mask + (size_t)row*64;

    #pragma unroll
    for (int t8 = 0; t8 < 8; t8++) {
        unsigned w[8];
        #pragma unroll
        for (int k = 0; k < 8; k++) {
            int v = __ldcs(ap + (t8*8 + k)*32);
            w[k] = __ballot_sync(0xffffffffu, v > 0);
        }
        if (lane == 0) {
            *(uint4*)(mp + t8*8)     = make_uint4(w[0], w[1], w[2], w[3]);
            *(uint4*)(mp + t8*8 + 4) = make_uint4(w[4], w[5], w[6], w[7]);
        }
    }
}

// ---------------- Kernel 2: per-(b,it,jc,h) unit, M=32 rows/warp ------------
// 128 threads (4 warps x 32 rows). Each B fragment feeds 4 MMAs -> LDSM halved.
#define SMEM_ATTN 39968
#define ONEH2 0x3C003C00u

__global__ __launch_bounds__(128,3) void k_attn()
{
    extern __shared__ char smem[];
    float*    s_il2e = (float*)(smem);
    float*    s_mhat = (float*)(smem + 512);
    float*    sjs    = (float*)(smem + 1024);
    unsigned* lutm   = (unsigned*)(smem + 3072);
    __half*   projB  = (__half*)(smem + 3104);
    uint32_t  projB_u32 = smem_u32(projB);

    int cidx = blockIdx.x;                 // 1024 units
    int it = cidx & 15;
    int jc = (cidx >> 4) & 3;
    int b  = (cidx >> 6) & 3;
    int h  = cidx >> 8;
    int tile = (b*16 + it)*4 + jc;

    int tid = threadIdx.x, lane = tid & 31, wid = tid >> 5;   // 4 warps
    int g = lane >> 2, tg2 = (lane & 3)*2;

    if (tid < 4)
        lutm[tid] = ((tid & 1) ? 0x00003C00u : 0u) | ((tid & 2) ? 0x3C000000u : 0u);

    {
        float sv = g_s[(size_t)(h*BB+b)*NN + it*128 + tid];
        float sp = g_spos[h*BB+b], sn = g_sneg[h*BB+b];
        float mh = (sv >= 0.f) ? sv*sp : sv*sn;
        s_il2e[tid] = sv * LOG2E;
        s_mhat[tid] = mh * LOG2E;
    }
    for (int idx = tid; idx < 512; idx += 128)
        sjs[idx] = g_s[(size_t)(h*BB+b)*NN + jc*JCHUNK + idx];

    auto loadB = [&](int jtn, int bufn) {
        const char* psrc = (const char*)(g_proj +
            ((size_t)(h*BB+b)*NN + jc*JCHUNK + jtn*128)*UU);
        uint32_t pdst = projB_u32 + (uint32_t)bufn*BUFB;
        #pragma unroll
        for (int c = 0; c < 8; c++) {
            int k = tid + c*128;
            int ro = k >> 3, cg = k & 7;
            CP_ASYNC_16(pdst + (uint32_t)(ro*BLD + cg*8)*2, psrc + (size_t)k*16);
        }
        CP_ASYNC_COMMIT();
    };

    loadB(0, 0);
    CP_ASYNC_WAIT0();
    __syncthreads();

    // 4 rows per lane: base + {0,8,16,24}
    int rbase = wid*32 + g;
    int r1 = rbase + 8, r2 = rbase + 16, r3 = rbase + 24;

    int ldm_row = (lane & 7) + ((lane >> 3) & 1)*8;
    uint32_t ldm_off = (uint32_t)(ldm_row*BLD + (lane >> 4)*8) * 2;

    const uint4* mr0 = (const uint4*)(g_mask + ((size_t)(b*NN + it*128 + rbase))*64 + jc*16);
    const uint4* mr1 = (const uint4*)(g_mask + ((size_t)(b*NN + it*128 + r1))*64 + jc*16);
    const uint4* mr2 = (const uint4*)(g_mask + ((size_t)(b*NN + it*128 + r2))*64 + jc*16);
    const uint4* mr3 = (const uint4*)(g_mask + ((size_t)(b*NN + it*128 + r3))*64 + jc*16);

    float srl0 = s_il2e[rbase], nmh0 = -s_mhat[rbase];
    float srl1 = s_il2e[r1],    nmh1 = -s_mhat[r1];
    float srl2 = s_il2e[r2],    nmh2 = -s_mhat[r2];
    float srl3 = s_il2e[r3],    nmh3 = -s_mhat[r3];

    float acc0[8][4], acc1[8][4];          // two 16-row groups
    float zac0[4], zac1[4];
    #pragma unroll
    for (int q = 0; q < 8; q++)
        #pragma unroll
        for (int i = 0; i < 4; i++) { acc0[q][i] = 0.f; acc1[q][i] = 0.f; }
    #pragma unroll
    for (int i = 0; i < 4; i++) { zac0[i] = 0.f; zac1[i] = 0.f; }

    #pragma unroll
    for (int jt = 0; jt < 4; jt++) {
        uint32_t bbase = projB_u32 + (uint32_t)(jt & 1)*BUFB + ldm_off;

        if (jt) { CP_ASYNC_WAIT0(); __syncthreads(); }
        if (jt + 1 < 4) loadB(jt + 1, (jt + 1) & 1);

        uint4 mw0 = mr0[jt], mw1 = mr1[jt], mw2 = mr2[jt], mw3 = mr3[jt];
        const float* sjp = sjs + jt*128;

        #pragma unroll
        for (int w = 0; w < 4; w++) {
            unsigned w0 = (w==0)?mw0.x:(w==1)?mw0.y:(w==2)?mw0.z:mw0.w;
            unsigned w1 = (w==0)?mw1.x:(w==1)?mw1.y:(w==2)?mw1.z:mw1.w;
            unsigned w2 = (w==0)?mw2.x:(w==1)?mw2.y:(w==2)?mw2.z:mw2.w;
            unsigned w3 = (w==0)?mw3.x:(w==1)?mw3.y:(w==2)?mw3.z:mw3.w;
            #pragma unroll
            for (int k2 = 0; k2 < 2; k2++) {
                int ks = w*2 + k2;
                int c0 = ks*16 + tg2;
                float2 sj0 = *(const float2*)(sjp + c0);
                float2 sj1 = *(const float2*)(sjp + c0 + 8);
                int sh = k2*16 + tg2;

                // group 0: rows rbase, r1
                uint32_t aA0 = hmul2u(
                    ex2pack(fmaf(srl0, sj0.x, nmh0), fmaf(srl0, sj0.y, nmh0)),
                    lutm[(w0 >> sh) & 3]);
                uint32_t aA1 = hmul2u(
                    ex2pack(fmaf(srl1, sj0.x, nmh1), fmaf(srl1, sj0.y, nmh1)),
                    lutm[(w1 >> sh) & 3]);
                uint32_t aA2 = hmul2u(
                    ex2pack(fmaf(srl0, sj1.x, nmh0), fmaf(srl0, sj1.y, nmh0)),
                    lutm[(w0 >> (sh+8)) & 3]);
                uint32_t aA3 = hmul2u(
                    ex2pack(fmaf(srl1, sj1.x, nmh1), fmaf(srl1, sj1.y, nmh1)),
                    lutm[(w1 >> (sh+8)) & 3]);
                // group 1: rows r2, r3
                uint32_t aB0 = hmul2u(
                    ex2pack(fmaf(srl2, sj0.x, nmh2), fmaf(srl2, sj0.y, nmh2)),
                    lutm[(w2 >> sh) & 3]);
                uint32_t aB1 = hmul2u(
                    ex2pack(fmaf(srl3, sj0.x, nmh3), fmaf(srl3, sj0.y, nmh3)),
                    lutm[(w3 >> sh) & 3]);
                uint32_t aB2 = hmul2u(
                    ex2pack(fmaf(srl2, sj1.x, nmh2), fmaf(srl2, sj1.y, nmh2)),
                    lutm[(w2 >> (sh+8)) & 3]);
                uint32_t aB3 = hmul2u(
                    ex2pack(fmaf(srl3, sj1.x, nmh3), fmaf(srl3, sj1.y, nmh3)),
                    lutm[(w3 >> (sh+8)) & 3]);

                uint32_t kroff = (uint32_t)(ks*16*BLD*2);
                #pragma unroll
                for (int nt = 0; nt < 4; nt++) {
                    uint32_t b0, b1, b2, b3;
                    LDSM_X4_TRANS(b0, b1, b2, b3, bbase + kroff + (uint32_t)(nt*16*2));
                    MMA_F16(acc0[2*nt],   aA0, aA1, aA2, aA3, b0, b1);
                    MMA_F16(acc0[2*nt+1], aA0, aA1, aA2, aA3, b2, b3);
                    MMA_F16(acc1[2*nt],   aB0, aB1, aB2, aB3, b0, b1);
                    MMA_F16(acc1[2*nt+1], aB0, aB1, aB2, aB3, b2, b3);
                }
                MMA_F16(zac0, aA0, aA1, aA2, aA3, ONEH2, ONEH2);
                MMA_F16(zac1, aB0, aB1, aB2, aB3, ONEH2, ONEH2);
            }
        }
    }

    __half* ob0 = g_Opart + (((size_t)tile*HH + h)*128 + wid*32)*64;
    __half* ob1 = ob0 + 16*64;
    #pragma unroll
    for (int q = 0; q < 8; q++) {
        *(__half2*)(ob0 + (size_t)g*64     + q*8 + tg2) = __floats2half2_rn(acc0[q][0], acc0[q][1]);
        *(__half2*)(ob0 + (size_t)(g+8)*64 + q*8 + tg2) = __floats2half2_rn(acc0[q][2], acc0[q][3]);
        *(__half2*)(ob1 + (size_t)g*64     + q*8 + tg2) = __floats2half2_rn(acc1[q][0], acc1[q][1]);
        *(__half2*)(ob1 + (size_t)(g+8)*64 + q*8 + tg2) = __floats2half2_rn(acc1[q][2], acc1[q][3]);
    }
    if ((lane & 3) == 0) {
        float* zb = g_Zpart + ((size_t)tile*HH + h)*128;
        zb[rbase] = zac0[0];
        zb[r1]    = zac0[2];
        zb[r2]    = zac1[0];
        zb[r3]    = zac1[2];
    }
}

// ---------------- Kernel 3: combine, divide, head-mean (1 thread / u-pair) --
__global__ __launch_bounds__(256) void k_final(float* __restrict__ out)
{
    int idx = blockIdx.x*256 + threadIdx.x;      // 0 .. 262143
    int u2 = idx & 31;
    int n  = (idx >> 5) & 2047;
    int b  = idx >> 16;
    int it = n >> 7, r = n & 127;

    float ax = 0.f, ay = 0.f;
    #pragma unroll
    for (int h = 0; h < HH; h++) {
        float z = 0.f, nx = 0.f, ny = 0.f;
        #pragma unroll
        for (int jcc = 0; jcc < JC; jcc++) {
            int c = (b*16 + it)*4 + jcc;
            size_t base = ((size_t)c*HH + h)*128 + r;
            z += g_Zpart[base];
            __half2 v = *(const __half2*)(g_Opart + base*64 + u2*2);
            float2 f = __half22float2(v);
            nx += f.x; ny += f.y;
        }
        float rz = __frcp_rn(z);
        ax = fmaf(nx, rz, ax);
        ay = fmaf(ny, rz, ay);
    }
    *(float2*)(out + ((size_t)b*NN + n)*64 + u2*2) = make_float2(0.25f*ax, 0.25f*ay);
}

// ---------------- launch (serial; stream-fork was a measured regression) ----
extern "C" void kernel_launch(void* const* d_in, const int* in_sizes, int n_in,
                              void* d_out, int out_size)
{
    const float* x   = (const float*)d_in[0];
    const int*   adj = (const int*)d_in[1];
    const float* W   = (const float*)d_in[2];
    const float* bia = (const float*)d_in[3];
    const float* aw  = (const float*)d_in[4];
    const float* ab  = (const float*)d_in[5];
    float* out = (float*)d_out;
    (void)in_sizes; (void)n_in; (void)out_size;

    cudaFuncSetAttribute(k_attn, cudaFuncAttributeMaxDynamicSharedMemorySize, SMEM_ATTN);

    dim3 g1(NN/128, BB, HH);
    k_proj<<<g1, 128>>>(x, W, bia, aw, ab);
    k_minmax<<<HH*BB, 256>>>();
    k_mask<<<1024, 256>>>(adj);
    k_attn<<<1024, 128, SMEM_ATTN>>>();
    k_final<<<(BB*NN*UU/2)/256, 256>>>(out);
}

// round 17
// speedup vs baseline: 1.2698x; 1.0276x over previous
#include <cuda_runtime.h>
#include <cuda_fp16.h>
#include <cstdint>

#define HH 4
#define BB 4
#define NN 2048
#define FF 128
#define UU 64
#define LOG2E 1.4426950408889634f

#define JC 4
#define JCHUNK 512
#define NTILE (BB*16*JC)   // 256 (b,it,jc) tiles
#define BLD 72             // proj B tile row stride in halves (144 B): conflict-free
#define BUFB (128*BLD*2)   // one B buffer: 18432 bytes

// ---------------- scratch ----------------------------------------------------
__device__ __half    g_proj[HH*BB*NN*UU];     // 4 MB  fp16 projections
__device__ float     g_s[HH*BB*NN];
__device__ float     g_spos[HH*BB];
__device__ float     g_sneg[HH*BB];
__device__ unsigned  g_mask[BB*NN*64];        // 2 MB packed adjacency bitmask
__device__ __half    g_Opart[8388608];        // [NTILE][H][128][64] fp16 partials
__device__ float     g_Zpart[NTILE*HH*128];

__device__ __forceinline__ uint32_t smem_u32(const void* p) {
    uint32_t a;
    asm("{ .reg .u64 t; cvta.to.shared.u64 t, %1; cvt.u32.u64 %0, t; }" : "=r"(a) : "l"(p));
    return a;
}

__device__ __forceinline__ uint32_t ex2pack(float x, float y) {
    __half2 hh = __floats2half2_rn(x, y);
    uint32_t u = *reinterpret_cast<uint32_t*>(&hh);
    asm("ex2.approx.f16x2 %0, %0;" : "+r"(u));
    return u;
}
__device__ __forceinline__ uint32_t hmul2u(uint32_t e, uint32_t m) {
    __half2 a = *reinterpret_cast<__half2*>(&e);
    __half2 b = *reinterpret_cast<__half2*>(&m);
    __half2 c = __hmul2(a, b);
    return *reinterpret_cast<uint32_t*>(&c);
}

#define MMA_F16(d, a0,a1,a2,a3, b0,b1) \
    asm volatile("mma.sync.aligned.m16n8k16.row.col.f32.f16.f16.f32 " \
        "{%0,%1,%2,%3}, {%4,%5,%6,%7}, {%8,%9}, {%0,%1,%2,%3};" \
        : "+f"((d)[0]), "+f"((d)[1]), "+f"((d)[2]), "+f"((d)[3]) \
        : "r"(a0), "r"(a1), "r"(a2), "r"(a3), "r"(b0), "r"(b1))

#define LDSM_X4_TRANS(r0,r1,r2,r3, addr) \
    asm volatile("ldmatrix.sync.aligned.m8n8.x4.trans.shared.b16 {%0,%1,%2,%3}, [%4];" \
        : "=r"(r0), "=r"(r1), "=r"(r2), "=r"(r3) : "r"(addr))

#define CP_ASYNC_16(dst_u32, src) \
    asm volatile("cp.async.cg.shared.global [%0], [%1], 16;" \
        :: "r"(dst_u32), "l"(src) : "memory")
#define CP_ASYNC_COMMIT() asm volatile("cp.async.commit_group;" ::: "memory")
#define CP_ASYNC_WAIT0()  asm volatile("cp.async.wait_group 0;" ::: "memory")

// ---------------- Kernel 1: proj = relu(x@W + b), s = proj.a_w + a_b --------
__global__ __launch_bounds__(128) void k_proj(const float* __restrict__ x,
                                              const float* __restrict__ W,
                                              const float* __restrict__ bias,
                                              const float* __restrict__ a_w,
                                              const float* __restrict__ a_b)
{
    __shared__ __align__(16) float Wsm[16][UU];
    __shared__ float xsm[128][17];
    __shared__ float bsm[UU], awsm[UU];

    int h = blockIdx.z, b = blockIdx.y;
    int n0 = blockIdx.x * 128;
    int tid = threadIdx.x;

    if (tid < UU) { bsm[tid] = bias[h*UU + tid]; awsm[tid] = a_w[h*UU + tid]; }

    unsigned long long acc2[32];
    #pragma unroll
    for (int p = 0; p < 32; p++) acc2[p] = 0ULL;

    const float* xb = x + ((size_t)b*NN + n0)*FF;
    const float* Wb = W + (size_t)h*FF*UU;

    for (int fc = 0; fc < FF; fc += 16) {
        __syncthreads();
        for (int k = tid; k < 16*UU; k += 128)
            Wsm[k>>6][k&63] = Wb[(size_t)(fc + (k>>6))*UU + (k&63)];
        for (int k = tid; k < 128*16; k += 128) {
            int r = k >> 4, f = k & 15;
            xsm[r][f] = xb[(size_t)r*FF + fc + f];
        }
        __syncthreads();
        #pragma unroll
        for (int f = 0; f < 16; f++) {
            float xv = xsm[tid][f];
            unsigned long long xv2;
            asm("mov.b64 %0, {%1, %1};" : "=l"(xv2) : "f"(xv));
            #pragma unroll
            for (int p = 0; p < 32; p += 2) {
                ulonglong2 w2 = *(const ulonglong2*)&Wsm[f][p*2];
                asm("fma.rn.f32x2 %0, %1, %2, %0;" : "+l"(acc2[p])   : "l"(xv2), "l"(w2.x));
                asm("fma.rn.f32x2 %0, %1, %2, %0;" : "+l"(acc2[p+1]) : "l"(xv2), "l"(w2.y));
            }
        }
    }

    float s = 0.f;
    __half2* pout = (__half2*)(g_proj + ((size_t)(h*BB+b)*NN + n0 + tid)*UU);
    #pragma unroll
    for (int p = 0; p < 32; p++) {
        float a0, a1;
        asm("mov.b64 {%0,%1}, %2;" : "=f"(a0), "=f"(a1) : "l"(acc2[p]));
        float p0 = fmaxf(a0 + bsm[2*p],   0.f);
        float p1 = fmaxf(a1 + bsm[2*p+1], 0.f);
        s = fmaf(p0, awsm[2*p],   s);
        s = fmaf(p1, awsm[2*p+1], s);
        pout[p] = __floats2half2_rn(p0, p1);
    }
    s += a_b[h];
    g_s[(size_t)(h*BB+b)*NN + n0 + tid] = s;
}

// ---------------- Kernel 1b: fused mask + minmax -----------------------------
// blocks [0,1024): adj -> bitmask via ballot (1 warp / row)
// blocks [1024,1040): per-(h,b) max/min of s
__global__ __launch_bounds__(256) void k_maskmin(const int* __restrict__ adj)
{
    int tid = threadIdx.x;
    if (blockIdx.x < 1024) {
        int wid = tid >> 5, lane = tid & 31;
        int row = blockIdx.x*8 + wid;          // 0..8191 = b*NN + i
        const int* ap = adj + (size_t)row*NN + lane;
        unsigned* mp = g_mask + (size_t)row*64;
        #pragma unroll
        for (int t8 = 0; t8 < 8; t8++) {
            unsigned w[8];
            #pragma unroll
            for (int k = 0; k < 8; k++) {
                int v = __ldcs(ap + (t8*8 + k)*32);
                w[k] = __ballot_sync(0xffffffffu, v > 0);
            }
            if (lane == 0) {
                *(uint4*)(mp + t8*8)     = make_uint4(w[0], w[1], w[2], w[3]);
                *(uint4*)(mp + t8*8 + 4) = make_uint4(w[4], w[5], w[6], w[7]);
            }
        }
        return;
    }

    __shared__ float smx[256], smn[256];
    int hb = blockIdx.x - 1024;
    float mx = -1e30f, mn = 1e30f;
    for (int k = tid; k < NN; k += 256) {
        float v = g_s[(size_t)hb*NN + k];
        mx = fmaxf(mx, v); mn = fminf(mn, v);
    }
    smx[tid] = mx; smn[tid] = mn;
    __syncthreads();
    for (int off = 128; off > 0; off >>= 1) {
        if (tid < off) {
            smx[tid] = fmaxf(smx[tid], smx[tid+off]);
            smn[tid] = fminf(smn[tid], smn[tid+off]);
        }
        __syncthreads();
    }
    if (tid == 0) { g_spos[hb] = smx[0]; g_sneg[hb] = smn[0]; }
}

// ---------------- Kernel 2: per-(b,it,jc,h) unit, M=32 rows/warp, occ 4 -----
#define SMEM_ATTN 39968
#define ONEH2 0x3C003C00u

__global__ __launch_bounds__(128,4) void k_attn()
{
    extern __shared__ char smem[];
    float*    s_il2e = (float*)(smem);
    float*    s_mhat = (float*)(smem + 512);
    float*    sjs    = (float*)(smem + 1024);
    unsigned* lutm   = (unsigned*)(smem + 3072);
    __half*   projB  = (__half*)(smem + 3104);
    uint32_t  projB_u32 = smem_u32(projB);

    int cidx = blockIdx.x;                 // 1024 units
    int it = cidx & 15;
    int jc = (cidx >> 4) & 3;
    int b  = (cidx >> 6) & 3;
    int h  = cidx >> 8;
    int tile = (b*16 + it)*4 + jc;

    int tid = threadIdx.x, lane = tid & 31, wid = tid >> 5;   // 4 warps
    int g = lane >> 2, tg2 = (lane & 3)*2;

    if (tid < 4)
        lutm[tid] = ((tid & 1) ? 0x00003C00u : 0u) | ((tid & 2) ? 0x3C000000u : 0u);

    {
        float sv = g_s[(size_t)(h*BB+b)*NN + it*128 + tid];
        float sp = g_spos[h*BB+b], sn = g_sneg[h*BB+b];
        float mh = (sv >= 0.f) ? sv*sp : sv*sn;
        s_il2e[tid] = sv * LOG2E;
        s_mhat[tid] = mh * LOG2E;
    }
    for (int idx = tid; idx < 512; idx += 128)
        sjs[idx] = g_s[(size_t)(h*BB+b)*NN + jc*JCHUNK + idx];

    auto loadB = [&](int jtn, int bufn) {
        const char* psrc = (const char*)(g_proj +
            ((size_t)(h*BB+b)*NN + jc*JCHUNK + jtn*128)*UU);
        uint32_t pdst = projB_u32 + (uint32_t)bufn*BUFB;
        #pragma unroll
        for (int c = 0; c < 8; c++) {
            int k = tid + c*128;
            int ro = k >> 3, cg = k & 7;
            CP_ASYNC_16(pdst + (uint32_t)(ro*BLD + cg*8)*2, psrc + (size_t)k*16);
        }
        CP_ASYNC_COMMIT();
    };

    loadB(0, 0);
    CP_ASYNC_WAIT0();
    __syncthreads();

    // 4 rows per lane: base + {0,8,16,24}
    int rbase = wid*32 + g;
    int r1 = rbase + 8, r2 = rbase + 16, r3 = rbase + 24;

    int ldm_row = (lane & 7) + ((lane >> 3) & 1)*8;
    uint32_t ldm_off = (uint32_t)(ldm_row*BLD + (lane >> 4)*8) * 2;

    // scalar mask pointers (L2-resident; reloaded per w to cut live regs)
    const unsigned* mr0 = g_mask + ((size_t)(b*NN + it*128 + rbase))*64 + jc*16;
    const unsigned* mr1 = g_mask + ((size_t)(b*NN + it*128 + r1))*64 + jc*16;
    const unsigned* mr2 = g_mask + ((size_t)(b*NN + it*128 + r2))*64 + jc*16;
    const unsigned* mr3 = g_mask + ((size_t)(b*NN + it*128 + r3))*64 + jc*16;

    float srl0 = s_il2e[rbase], nmh0 = -s_mhat[rbase];
    float srl1 = s_il2e[r1],    nmh1 = -s_mhat[r1];
    float srl2 = s_il2e[r2],    nmh2 = -s_mhat[r2];
    float srl3 = s_il2e[r3],    nmh3 = -s_mhat[r3];

    float acc0[8][4], acc1[8][4];          // two 16-row groups
    float zac0[4], zac1[4];
    #pragma unroll
    for (int q = 0; q < 8; q++)
        #pragma unroll
        for (int i = 0; i < 4; i++) { acc0[q][i] = 0.f; acc1[q][i] = 0.f; }
    #pragma unroll
    for (int i = 0; i < 4; i++) { zac0[i] = 0.f; zac1[i] = 0.f; }

    #pragma unroll
    for (int jt = 0; jt < 4; jt++) {
        uint32_t bbase = projB_u32 + (uint32_t)(jt & 1)*BUFB + ldm_off;

        if (jt) { CP_ASYNC_WAIT0(); __syncthreads(); }
        if (jt + 1 < 4) loadB(jt + 1, (jt + 1) & 1);

        const float* sjp = sjs + jt*128;

        #pragma unroll
        for (int w = 0; w < 4; w++) {
            unsigned w0 = __ldg(mr0 + jt*4 + w);
            unsigned w1 = __ldg(mr1 + jt*4 + w);
            unsigned w2 = __ldg(mr2 + jt*4 + w);
            unsigned w3 = __ldg(mr3 + jt*4 + w);
            #pragma unroll
            for (int k2 = 0; k2 < 2; k2++) {
                int ks = w*2 + k2;
                int c0 = ks*16 + tg2;
                float2 sj0 = *(const float2*)(sjp + c0);
                float2 sj1 = *(const float2*)(sjp + c0 + 8);
                int sh = k2*16 + tg2;

                uint32_t aA0 = hmul2u(
                    ex2pack(fmaf(srl0, sj0.x, nmh0), fmaf(srl0, sj0.y, nmh0)),
                    lutm[(w0 >> sh) & 3]);
                uint32_t aA1 = hmul2u(
                    ex2pack(fmaf(srl1, sj0.x, nmh1), fmaf(srl1, sj0.y, nmh1)),
                    lutm[(w1 >> sh) & 3]);
                uint32_t aA2 = hmul2u(
                    ex2pack(fmaf(srl0, sj1.x, nmh0), fmaf(srl0, sj1.y, nmh0)),
                    lutm[(w0 >> (sh+8)) & 3]);
                uint32_t aA3 = hmul2u(
                    ex2pack(fmaf(srl1, sj1.x, nmh1), fmaf(srl1, sj1.y, nmh1)),
                    lutm[(w1 >> (sh+8)) & 3]);
                uint32_t aB0 = hmul2u(
                    ex2pack(fmaf(srl2, sj0.x, nmh2), fmaf(srl2, sj0.y, nmh2)),
                    lutm[(w2 >> sh) & 3]);
                uint32_t aB1 = hmul2u(
                    ex2pack(fmaf(srl3, sj0.x, nmh3), fmaf(srl3, sj0.y, nmh3)),
                    lutm[(w3 >> sh) & 3]);
                uint32_t aB2 = hmul2u(
                    ex2pack(fmaf(srl2, sj1.x, nmh2), fmaf(srl2, sj1.y, nmh2)),
                    lutm[(w2 >> (sh+8)) & 3]);
                uint32_t aB3 = hmul2u(
                    ex2pack(fmaf(srl3, sj1.x, nmh3), fmaf(srl3, sj1.y, nmh3)),
                    lutm[(w3 >> (sh+8)) & 3]);

                uint32_t kroff = (uint32_t)(ks*16*BLD*2);
                #pragma unroll
                for (int nt = 0; nt < 4; nt++) {
                    uint32_t b0, b1, b2, b3;
                    LDSM_X4_TRANS(b0, b1, b2, b3, bbase + kroff + (uint32_t)(nt*16*2));
                    MMA_F16(acc0[2*nt],   aA0, aA1, aA2, aA3, b0, b1);
                    MMA_F16(acc0[2*nt+1], aA0, aA1, aA2, aA3, b2, b3);
                    MMA_F16(acc1[2*nt],   aB0, aB1, aB2, aB3, b0, b1);
                    MMA_F16(acc1[2*nt+1], aB0, aB1, aB2, aB3, b2, b3);
                }
                MMA_F16(zac0, aA0, aA1, aA2, aA3, ONEH2, ONEH2);
                MMA_F16(zac1, aB0, aB1, aB2, aB3, ONEH2, ONEH2);
            }
        }
    }

    __half* ob0 = g_Opart + (((size_t)tile*HH + h)*128 + wid*32)*64;
    __half* ob1 = ob0 + 16*64;
    #pragma unroll
    for (int q = 0; q < 8; q++) {
        *(__half2*)(ob0 + (size_t)g*64     + q*8 + tg2) = __floats2half2_rn(acc0[q][0], acc0[q][1]);
        *(__half2*)(ob0 + (size_t)(g+8)*64 + q*8 + tg2) = __floats2half2_rn(acc0[q][2], acc0[q][3]);
        *(__half2*)(ob1 + (size_t)g*64     + q*8 + tg2) = __floats2half2_rn(acc1[q][0], acc1[q][1]);
        *(__half2*)(ob1 + (size_t)(g+8)*64 + q*8 + tg2) = __floats2half2_rn(acc1[q][2], acc1[q][3]);
    }
    if ((lane & 3) == 0) {
        float* zb = g_Zpart + ((size_t)tile*HH + h)*128;
        zb[rbase] = zac0[0];
        zb[r1]    = zac0[2];
        zb[r2]    = zac1[0];
        zb[r3]    = zac1[2];
    }
}

// ---------------- Kernel 3: combine, divide, head-mean (1 thread / u-pair) --
__global__ __launch_bounds__(256) void k_final(float* __restrict__ out)
{
    int idx = blockIdx.x*256 + threadIdx.x;      // 0 .. 262143
    int u2 = idx & 31;
    int n  = (idx >> 5) & 2047;
    int b  = idx >> 16;
    int it = n >> 7, r = n & 127;

    float ax = 0.f, ay = 0.f;
    #pragma unroll
    for (int h = 0; h < HH; h++) {
        float z = 0.f, nx = 0.f, ny = 0.f;
        #pragma unroll
        for (int jcc = 0; jcc < JC; jcc++) {
            int c = (b*16 + it)*4 + jcc;
            size_t base = ((size_t)c*HH + h)*128 + r;
            z += g_Zpart[base];
            __half2 v = *(const __half2*)(g_Opart + base*64 + u2*2);
            float2 f = __half22float2(v);
            nx += f.x; ny += f.y;
        }
        float rz = __frcp_rn(z);
        ax = fmaf(nx, rz, ax);
        ay = fmaf(ny, rz, ay);
    }
    *(float2*)(out + ((size_t)b*NN + n)*64 + u2*2) = make_float2(0.25f*ax, 0.25f*ay);
}

// ---------------- launch -----------------------------------------------------
extern "C" void kernel_launch(void* const* d_in, const int* in_sizes, int n_in,
                              void* d_out, int out_size)
{
    const float* x   = (const float*)d_in[0];
    const int*   adj = (const int*)d_in[1];
    const float* W   = (const float*)d_in[2];
    const float* bia = (const float*)d_in[3];
    const float* aw  = (const float*)d_in[4];
    const float* ab  = (const float*)d_in[5];
    float* out = (float*)d_out;
    (void)in_sizes; (void)n_in; (void)out_size;

    cudaFuncSetAttribute(k_attn, cudaFuncAttributeMaxDynamicSharedMemorySize, SMEM_ATTN);

    dim3 g1(NN/128, BB, HH);
    k_proj<<<g1, 128>>>(x, W, bia, aw, ab);
    k_maskmin<<<1040, 256>>>(adj);
    k_attn<<<1024, 128, SMEM_ATTN>>>();
    k_final<<<(BB*NN*UU/2)/256, 256>>>(out);
}